// round 15
// baseline (speedup 1.0000x reference)
#include <cuda_runtime.h>
#include <cuda_fp16.h>
#include <cstdint>

// Problem constants
#define B_  8
#define C_  128
#define H_  256
#define W_  256
#define KB_ 4
#define OC_ 128

// Scratch (static device arrays; no allocation)
__device__ float g_pooled[B_ * C_];
__device__ float g_dynk[B_ * C_ * 9];
// pw_w rounded to fp16, packed in m16n8k16 B-fragment order:
// [ci(8)][nt(16)][lane(32)] x uint2 {b0, b1}
__device__ uint2 g_pwf16[8 * 16 * 32];

// ---------------------------------------------------------------------------
// helpers
// ---------------------------------------------------------------------------
__device__ __forceinline__ uint32_t smem_u32(const void* p) {
    uint32_t a;
    asm("{ .reg .u64 t; cvta.to.shared.u64 t, %1; cvt.u32.u64 %0, t; }"
        : "=r"(a) : "l"(p));
    return a;
}
__device__ __forceinline__ void mma_f16(float* d, const uint32_t* a,
                                        uint32_t b0, uint32_t b1) {
    asm volatile(
        "mma.sync.aligned.m16n8k16.row.col.f32.f16.f16.f32 "
        "{%0,%1,%2,%3}, {%4,%5,%6,%7}, {%8,%9}, {%0,%1,%2,%3};"
        : "+f"(d[0]), "+f"(d[1]), "+f"(d[2]), "+f"(d[3])
        : "r"(a[0]), "r"(a[1]), "r"(a[2]), "r"(a[3]), "r"(b0), "r"(b1));
}

// ---------------------------------------------------------------------------
// Kernel 1: global average pool
// ---------------------------------------------------------------------------
__global__ void pool_kernel(const float* __restrict__ x) {
    const int plane = blockIdx.x;
    const int t = threadIdx.x;
    const float4* p = reinterpret_cast<const float4*>(x + (size_t)plane * (H_ * W_));
    float s = 0.f;
#pragma unroll 8
    for (int it = 0; it < 64; it++) {
        float4 v = p[it * 256 + t];
        s += (v.x + v.y) + (v.z + v.w);
    }
    __shared__ float red[256];
    red[t] = s;
    __syncthreads();
    for (int st = 128; st > 0; st >>= 1) {
        if (t < st) red[t] += red[t + st];
        __syncthreads();
    }
    if (t == 0) g_pooled[plane] = red[0] * (1.f / (H_ * W_));
}

// ---------------------------------------------------------------------------
// Kernel 2: attention -> softmax -> dynamic depthwise kernel per (b,c)
// ---------------------------------------------------------------------------
__global__ void attn_kernel(const float* __restrict__ kernel_bank,
                            const float* __restrict__ attn_w,
                            const float* __restrict__ attn_b) {
    const int b = blockIdx.x;
    const int c = threadIdx.x;               // 128 threads
    __shared__ float red[128];
    __shared__ float logit[KB_];
    __shared__ float attn[KB_];

    float p = g_pooled[b * C_ + c];
    for (int k = 0; k < KB_; k++) {
        red[c] = p * attn_w[k * C_ + c];
        __syncthreads();
        for (int st = 64; st > 0; st >>= 1) {
            if (c < st) red[c] += red[c + st];
            __syncthreads();
        }
        if (c == 0) logit[k] = red[0] + attn_b[k];
        __syncthreads();
    }
    if (c == 0) {
        float mx = logit[0];
        for (int k = 1; k < KB_; k++) mx = fmaxf(mx, logit[k]);
        float s = 0.f;
        for (int k = 0; k < KB_; k++) { attn[k] = expf(logit[k] - mx); s += attn[k]; }
        float inv = 1.f / s;
        for (int k = 0; k < KB_; k++) attn[k] *= inv;
    }
    __syncthreads();
    float a0 = attn[0], a1 = attn[1], a2 = attn[2], a3 = attn[3];
#pragma unroll
    for (int ij = 0; ij < 9; ij++) {
        float s = a0 * kernel_bank[(0 * C_ + c) * 9 + ij]
                + a1 * kernel_bank[(1 * C_ + c) * 9 + ij]
                + a2 * kernel_bank[(2 * C_ + c) * 9 + ij]
                + a3 * kernel_bank[(3 * C_ + c) * 9 + ij];
        g_dynk[(b * C_ + c) * 9 + ij] = s;
    }
}

// ---------------------------------------------------------------------------
// Kernel 2b: round pw_w to fp16, packed in B-fragment order.
// ---------------------------------------------------------------------------
__global__ void split_pw_fp16(const float* __restrict__ pw_w) {
    int idx = blockIdx.x * 256 + threadIdx.x;   // (ci, nt, lane)
    if (idx >= 4096) return;
    int lane = idx & 31;
    int nt   = (idx >> 5) & 15;
    int ci   = idx >> 9;
    int g = lane >> 2, tig = lane & 3;
    int o  = nt * 8 + g;
    int k0 = ci * 16 + 2 * tig;

    uint32_t b0 = (uint32_t)__half_as_ushort(__float2half_rn(pw_w[o * C_ + k0]))
                | ((uint32_t)__half_as_ushort(__float2half_rn(pw_w[o * C_ + k0 + 1])) << 16);
    uint32_t b1 = (uint32_t)__half_as_ushort(__float2half_rn(pw_w[o * C_ + k0 + 8]))
                | ((uint32_t)__half_as_ushort(__float2half_rn(pw_w[o * C_ + k0 + 9])) << 16);
    g_pwf16[idx] = make_uint2(b0, b1);
}

// ---------------------------------------------------------------------------
// Fused dw 3x3 + mma.sync fp16 GEMM (single-fp16 A, fp16 B).
// Grid (W/32=8, H/2=128, B=8), 256 threads, 3 CTAs/SM.
// CTA tile: M=64 = 32 px x 2 output rows, N=128 ocs.
// K processed in 4 SUPERCHUNKS of 32 channels (2 k16 MMA steps each):
// one barrier + one wait_group per 32 channels (half the loop overhead).
// dw on warps 0-3: thread (kch, pxg) computes 4 px x 2 rows x 2 channels
// (kch and kch+16) from 4 staged rows each.
// Smem (floats):
//   As[2]  : per buf 2 ksets x (512 + 16 pad) = 1056; 2 bufs = 2112
//   xs[2]  : 32 ch x 164; 2 bufs = 10496
//   dk     : 1152
// Total 13760 floats = 55040 B -> 3 CTAs/SM.
// ---------------------------------------------------------------------------
#define XS_ROW   40
#define XS_CH    164
#define XS_FLTS  (32 * XS_CH)               // 5248 per superchunk buffer
#define AS_F     0
#define AS_KSET  528
#define AS_STRIDE 1056
#define XS_F     (2 * AS_STRIDE)            // 2112
#define DK_F     (XS_F + 2 * XS_FLTS)       // 12608
#define SMEM_FLOATS (DK_F + 1152)           // 13760 -> 55040 B

__device__ __forceinline__ void stage_xs32(const float* __restrict__ x,
                                           int b, int c0, int h0, int w0,
                                           float* xf, int t) {
    // interior: 32 ch x 4 rows x 8 float4 = 1024 f4, 4 per thread
#pragma unroll
    for (int i = 0; i < 4; i++) {
        int idx = t + i * 256;
        int c   = idx >> 5;
        int rem = idx & 31;
        int r   = rem >> 3;
        int q   = rem & 7;
        int hh  = h0 + r - 1;
        float* dst = xf + c * XS_CH + r * XS_ROW + 4 + q * 4;
        if ((unsigned)hh < (unsigned)H_) {
            const float* src = x + (((size_t)(b * C_ + c0 + c)) * H_ + hh) * W_ + w0 + q * 4;
            asm volatile("cp.async.cg.shared.global [%0], [%1], 16;"
                         :: "r"(smem_u32(dst)), "l"(src));
        } else {
            *reinterpret_cast<float4*>(dst) = make_float4(0.f, 0.f, 0.f, 0.f);
        }
    }
    // halo columns: 32 ch x 4 rows x 2 sides = 256 scalars, 1 per thread
    {
        int c    = t >> 3;
        int rem  = t & 7;
        int r    = rem >> 1;
        int side = rem & 1;
        int hh   = h0 + r - 1;
        int ww   = side ? (w0 + 32) : (w0 - 1);
        int col  = side ? 36 : 3;
        float* dst = xf + c * XS_CH + r * XS_ROW + col;
        if ((unsigned)hh < (unsigned)H_ && (unsigned)ww < (unsigned)W_) {
            const float* src = x + (((size_t)(b * C_ + c0 + c)) * H_ + hh) * W_ + ww;
            asm volatile("cp.async.ca.shared.global [%0], [%1], 4;"
                         :: "r"(smem_u32(dst)), "l"(src));
        } else {
            *dst = 0.f;
        }
    }
}

// depthwise for one 16-ch k-set: 4 px x 2 rows per thread (row reuse)
__device__ __forceinline__ void dw_kset(const float* __restrict__ xch,
                                        const float* __restrict__ dkc,
                                        float* __restrict__ adst,
                                        int wb0, bool store) {
    float s0[4], s1[4];
#pragma unroll
    for (int j = 0; j < 4; j++) { s0[j] = 0.f; s1[j] = 0.f; }
#pragma unroll
    for (int r = 0; r < 4; r++) {
        const float* rp = xch + r * XS_ROW;
        float4 q0 = *reinterpret_cast<const float4*>(rp);
        float4 q1 = *reinterpret_cast<const float4*>(rp + 4);
        float s8  = rp[8];
        float v[9] = {q0.x, q0.y, q0.z, q0.w, q1.x, q1.y, q1.z, q1.w, s8};
        if (r < 3) {
            float k0 = dkc[r * 3 + 0], k1 = dkc[r * 3 + 1], k2 = dkc[r * 3 + 2];
#pragma unroll
            for (int j = 0; j < 4; j++) {
                s0[j] = fmaf(k0, v[j + 3], s0[j]);
                s0[j] = fmaf(k1, v[j + 4], s0[j]);
                s0[j] = fmaf(k2, v[j + 5], s0[j]);
            }
        }
        if (r > 0) {
            float k0 = dkc[(r - 1) * 3 + 0], k1 = dkc[(r - 1) * 3 + 1],
                  k2 = dkc[(r - 1) * 3 + 2];
#pragma unroll
            for (int j = 0; j < 4; j++) {
                s1[j] = fmaf(k0, v[j + 3], s1[j]);
                s1[j] = fmaf(k1, v[j + 4], s1[j]);
                s1[j] = fmaf(k2, v[j + 5], s1[j]);
            }
        }
    }
#pragma unroll
    for (int j = 0; j < 4; j++) {
        uint32_t own = (uint32_t)__half_as_ushort(__float2half_rn(s0[j]));
        uint32_t partner = __shfl_xor_sync(0xffffffffu, own, 1);
        if (store)
            adst[wb0 + j * 16] =
                __uint_as_float(__byte_perm(own, partner, 0x5410));
    }
#pragma unroll
    for (int j = 0; j < 4; j++) {
        uint32_t own = (uint32_t)__half_as_ushort(__float2half_rn(s1[j]));
        uint32_t partner = __shfl_xor_sync(0xffffffffu, own, 1);
        if (store)
            adst[wb0 + 256 + j * 16] =       // row 1: mt += 2 -> +256 words
                __uint_as_float(__byte_perm(own, partner, 0x5410));
    }
}

// depthwise superchunk sc: 2 channels per thread (kch, kch+16)
__device__ __forceinline__ void dw_super(float* smem, int sc, int kch, int pxg,
                                         int wb0, bool store) {
    const float* dk  = smem + DK_F;
    const float* xsb = smem + XS_F + (sc & 1) * XS_FLTS;
    float* asb       = smem + AS_F + (sc & 1) * AS_STRIDE;
#pragma unroll
    for (int ch2 = 0; ch2 < 2; ch2++) {
        const int ch = ch2 * 16 + kch;
        dw_kset(xsb + ch * XS_CH + pxg * 4,
                dk + (sc * 32 + ch) * 9,
                asb + ch2 * AS_KSET, wb0, store);
    }
}

__global__ __launch_bounds__(256, 3)
void fused_kernel(const float* __restrict__ x,
                  const float* __restrict__ pw_b,
                  float* __restrict__ out) {
    extern __shared__ float smem[];
    float* dk = smem + DK_F;

    const int t    = threadIdx.x;
    const int wid  = t >> 5;
    const int lane = t & 31;
    const int w0   = blockIdx.x * 32;
    const int h0   = blockIdx.y * 2;
    const int bb   = blockIdx.z;

    // dw mapping (threads 0-127): channel kch, px group pxg (4 px, both rows)
    const int kch = t & 15;
    const int pxg = (t >> 4) & 7;
    const bool is_dw = (t < 128);
    const int wb0 = (pxg >> 2) * 128 + (pxg & 1) * 64
                  + ((kch >> 1) & 3) * 4 + (kch >> 3) * 2 + ((pxg >> 1) & 1);
    const bool a_store = is_dw && ((kch & 1) == 0);

    // GEMM warp tiling: 2 m-warps x 4 n-warps, warp tile m32 x n32
    const int wm = wid & 1;
    const int wn = wid >> 1;
    const uint2* bsrc = g_pwf16 + (wn * 4) * 32 + lane;

    // prologue
    stage_xs32(x, bb, 0, h0, w0, smem + XS_F, t);
    asm volatile("cp.async.commit_group;" ::: "memory");
    for (int i = t; i < C_ * 9; i += 256)
        dk[i] = g_dynk[bb * C_ * 9 + i];

    float acc[2][4][4];
#pragma unroll
    for (int i = 0; i < 2; i++)
#pragma unroll
        for (int j = 0; j < 4; j++)
#pragma unroll
            for (int k = 0; k < 4; k++) acc[i][j][k] = 0.f;

    asm volatile("cp.async.wait_group 0;" ::: "memory");
    __syncthreads();
    stage_xs32(x, bb, 32, h0, w0, smem + XS_F + XS_FLTS, t);
    asm volatile("cp.async.commit_group;" ::: "memory");

    if (is_dw) dw_super(smem, 0, kch, pxg, wb0, a_store);

#pragma unroll 1
    for (int sc = 0; sc < 4; sc++) {
        if (sc < 3)
            asm volatile("cp.async.wait_group 0;" ::: "memory");
        __syncthreads();   // dw(sc) visible; GEMM(sc-1) done with As[(sc+1)&1]

        // B fragments for both ksets of sc (latency covered by dw below)
        uint2 bfrag[2][4];
#pragma unroll
        for (int ks = 0; ks < 2; ks++)
#pragma unroll
            for (int ntl = 0; ntl < 4; ntl++)
                bfrag[ks][ntl] = __ldg(bsrc + (sc * 2 + ks) * 512 + ntl * 32);

        if (sc < 2) {
            stage_xs32(x, bb, (sc + 2) * 32, h0, w0,
                       smem + XS_F + (sc & 1) * XS_FLTS, t);
            asm volatile("cp.async.commit_group;" ::: "memory");
        }

        // dw(sc+1) overlaps GEMM(sc) across warps
        if (sc < 3 && is_dw)
            dw_super(smem, sc + 1, kch, pxg, wb0, a_store);

        // --- GEMM(sc): two k16 MMA steps ---
        {
            const float* asb = smem + AS_F + (sc & 1) * AS_STRIDE;
#pragma unroll
            for (int ks = 0; ks < 2; ks++) {
                uint4 ah[2];
#pragma unroll
                for (int mA = 0; mA < 2; mA++) {
                    int fi = ((wm * 2 + mA) * 32 + lane) * 4;
                    ah[mA] = *reinterpret_cast<const uint4*>(asb + ks * AS_KSET + fi);
                }
#pragma unroll
                for (int ntl = 0; ntl < 4; ntl++) {
                    uint2 bv = bfrag[ks][ntl];
#pragma unroll
                    for (int mA = 0; mA < 2; mA++)
                        mma_f16(acc[mA][ntl], reinterpret_cast<uint32_t*>(&ah[mA]),
                                bv.x, bv.y);
                }
            }
        }
    }

    // --- epilogue: D fragment scatter + bias ---
    const int g   = lane >> 2;
    const int tig = lane & 3;
#pragma unroll
    for (int mA = 0; mA < 2; mA++) {
        int mt = wm * 2 + mA;
        int h  = h0 + (mt >> 1);
        int wp = w0 + (mt & 1) * 16;
#pragma unroll
        for (int ntl = 0; ntl < 4; ntl++) {
            int o = (wn * 4 + ntl) * 8 + 2 * tig;
            float b0v = __ldg(pw_b + o);
            float b1v = __ldg(pw_b + o + 1);
            size_t r0 = (((size_t)(bb * OC_ + o)) * H_ + h) * W_ + wp;
            size_t r1 = r0 + (size_t)H_ * W_;
            const float* a4 = acc[mA][ntl];
            out[r0 + g]     = a4[0] + b0v;
            out[r1 + g]     = a4[1] + b1v;
            out[r0 + g + 8] = a4[2] + b0v;
            out[r1 + g + 8] = a4[3] + b1v;
        }
    }
}

// ---------------------------------------------------------------------------
extern "C" void kernel_launch(void* const* d_in, const int* in_sizes, int n_in,
                              void* d_out, int out_size) {
    const float* x           = (const float*)d_in[0];
    const float* kernel_bank = (const float*)d_in[1];
    const float* attn_w      = (const float*)d_in[2];
    const float* attn_b      = (const float*)d_in[3];
    const float* pw_w        = (const float*)d_in[4];
    const float* pw_b        = (const float*)d_in[5];
    float* out               = (float*)d_out;

    static int smem_set = 0;
    if (!smem_set) {
        cudaFuncSetAttribute(fused_kernel,
                             cudaFuncAttributeMaxDynamicSharedMemorySize,
                             SMEM_FLOATS * 4);
        smem_set = 1;
    }

    pool_kernel<<<B_ * C_, 256>>>(x);
    attn_kernel<<<B_, 128>>>(kernel_bank, attn_w, attn_b);
    split_pw_fp16<<<16, 256>>>(pw_w);
    fused_kernel<<<dim3(W_ / 32, H_ / 2, B_), 256, SMEM_FLOATS * 4>>>(x, pw_b, out);
}

// round 16
// speedup vs baseline: 1.4371x; 1.4371x over previous
#include <cuda_runtime.h>
#include <cuda_fp16.h>
#include <cstdint>

// Problem constants
#define B_  8
#define C_  128
#define H_  256
#define W_  256
#define KB_ 4
#define OC_ 128

// Scratch (static device arrays; no allocation)
__device__ float g_pooled[B_ * C_];
__device__ float g_dynk[B_ * C_ * 9];
// pw_w rounded to fp16, packed in m16n8k16 B-fragment order:
// [ci(8)][nt(16)][lane(32)] x uint2 {b0, b1}
__device__ uint2 g_pwf16[8 * 16 * 32];

// ---------------------------------------------------------------------------
// helpers
// ---------------------------------------------------------------------------
__device__ __forceinline__ uint32_t smem_u32(const void* p) {
    uint32_t a;
    asm("{ .reg .u64 t; cvta.to.shared.u64 t, %1; cvt.u32.u64 %0, t; }"
        : "=r"(a) : "l"(p));
    return a;
}
__device__ __forceinline__ void mma_f16(float* d, const uint32_t* a,
                                        uint32_t b0, uint32_t b1) {
    asm volatile(
        "mma.sync.aligned.m16n8k16.row.col.f32.f16.f16.f32 "
        "{%0,%1,%2,%3}, {%4,%5,%6,%7}, {%8,%9}, {%0,%1,%2,%3};"
        : "+f"(d[0]), "+f"(d[1]), "+f"(d[2]), "+f"(d[3])
        : "r"(a[0]), "r"(a[1]), "r"(a[2]), "r"(a[3]), "r"(b0), "r"(b1));
}

// ---------------------------------------------------------------------------
// Kernel 1: global average pool
// ---------------------------------------------------------------------------
__global__ void pool_kernel(const float* __restrict__ x) {
    const int plane = blockIdx.x;
    const int t = threadIdx.x;
    const float4* p = reinterpret_cast<const float4*>(x + (size_t)plane * (H_ * W_));
    float s = 0.f;
#pragma unroll 8
    for (int it = 0; it < 64; it++) {
        float4 v = p[it * 256 + t];
        s += (v.x + v.y) + (v.z + v.w);
    }
    __shared__ float red[256];
    red[t] = s;
    __syncthreads();
    for (int st = 128; st > 0; st >>= 1) {
        if (t < st) red[t] += red[t + st];
        __syncthreads();
    }
    if (t == 0) g_pooled[plane] = red[0] * (1.f / (H_ * W_));
}

// ---------------------------------------------------------------------------
// Kernel 2 (merged): blocks 0-7: attention -> softmax -> dynamic dw kernel;
// blocks 8-23: round pw_w to fp16 in B-fragment order.
// ---------------------------------------------------------------------------
__global__ void prep_kernel(const float* __restrict__ kernel_bank,
                            const float* __restrict__ attn_w,
                            const float* __restrict__ attn_b,
                            const float* __restrict__ pw_w) {
    if (blockIdx.x >= 8) {
        // --- split pw_w to fp16 B-fragments ---
        int idx = (blockIdx.x - 8) * 256 + threadIdx.x;   // (ci, nt, lane)
        int lane = idx & 31;
        int nt   = (idx >> 5) & 15;
        int ci   = idx >> 9;
        int g = lane >> 2, tig = lane & 3;
        int o  = nt * 8 + g;
        int k0 = ci * 16 + 2 * tig;
        uint32_t b0 = (uint32_t)__half_as_ushort(__float2half_rn(pw_w[o * C_ + k0]))
                    | ((uint32_t)__half_as_ushort(__float2half_rn(pw_w[o * C_ + k0 + 1])) << 16);
        uint32_t b1 = (uint32_t)__half_as_ushort(__float2half_rn(pw_w[o * C_ + k0 + 8]))
                    | ((uint32_t)__half_as_ushort(__float2half_rn(pw_w[o * C_ + k0 + 9])) << 16);
        g_pwf16[idx] = make_uint2(b0, b1);
        return;
    }
    // --- attention + dynamic kernel (uses threads 0-127) ---
    const int b = blockIdx.x;
    const int c = threadIdx.x;
    __shared__ float red[128];
    __shared__ float logit[KB_];
    __shared__ float attn[KB_];
    if (c < 128) {
        float p = g_pooled[b * C_ + c];
        for (int k = 0; k < KB_; k++) {
            red[c] = p * attn_w[k * C_ + c];
            __syncwarp();
            // block has 256 threads but only 0-127 participate in reduction;
            // use explicit fences via __syncthreads below instead.
            __syncthreads();
            if (c < 64) red[c] += red[c + 64];
            __syncthreads();
            if (c < 32) red[c] += red[c + 32];
            __syncthreads();
            if (c < 32) {
                float v = red[c];
#pragma unroll
                for (int st = 16; st > 0; st >>= 1)
                    v += __shfl_down_sync(0xffffffffu, v, st);
                if (c == 0) logit[k] = v + attn_b[k];
            }
            __syncthreads();
        }
        if (c == 0) {
            float mx = logit[0];
            for (int k = 1; k < KB_; k++) mx = fmaxf(mx, logit[k]);
            float s = 0.f;
            for (int k = 0; k < KB_; k++) { attn[k] = expf(logit[k] - mx); s += attn[k]; }
            float inv = 1.f / s;
            for (int k = 0; k < KB_; k++) attn[k] *= inv;
        }
        __syncthreads();
        float a0 = attn[0], a1 = attn[1], a2 = attn[2], a3 = attn[3];
#pragma unroll
        for (int ij = 0; ij < 9; ij++) {
            float s = a0 * kernel_bank[(0 * C_ + c) * 9 + ij]
                    + a1 * kernel_bank[(1 * C_ + c) * 9 + ij]
                    + a2 * kernel_bank[(2 * C_ + c) * 9 + ij]
                    + a3 * kernel_bank[(3 * C_ + c) * 9 + ij];
            g_dynk[(b * C_ + c) * 9 + ij] = s;
        }
    } else {
        // threads 128-255 just participate in the __syncthreads calls
        for (int k = 0; k < KB_; k++) { __syncthreads(); __syncthreads(); __syncthreads(); }
        __syncthreads();
    }
}

// ---------------------------------------------------------------------------
// Fused dw 3x3 + mma.sync fp16 GEMM (single-fp16 A, fp16 B).
// Grid (W/32=8, H/2=128, B=8), 256 threads, 3 CTAs/SM.
// CTA tile: M=64 = 32 px x 2 output rows, N=128 ocs.
// xs staged as unified rows: 10 float4 per row covering w0-4..w0+35
// (smem col s = global w0 + s - 4; taps for px m at cols m+3..m+5).
// dw on warps 0-3: thread (kch, pxg) computes 4 px x 2 rows from 4 rows.
// dk stored stride-12 -> 3x LDS.128 per chunk.
// Smem (floats):
//   As[2] : 512 words + 16 pad each (stride 528)
//   xs[2] : 16 ch x 4 rows x 40, ch stride 164 fl (41 16B-units, odd -> CF)
//   dk    : 128 x 12
// ---------------------------------------------------------------------------
#define XS_ROW   40
#define XS_CH    164
#define XS_FLTS  (16 * XS_CH)               // 2624 per buffer
#define AS_F     0
#define AS_STRIDE 528
#define XS_F     (2 * AS_STRIDE)            // 1056
#define DK_F     (XS_F + 2 * XS_FLTS)       // 6304
#define SMEM_FLOATS (DK_F + 128 * 12)       // 7840 -> 31360 B

__device__ __forceinline__ void stage_xs(const float* __restrict__ x,
                                         int b, int c0, int h0, int w0,
                                         float* xf, int t) {
    // 16 ch x 4 rows x 10 float4 = 640 ops (covers halo + interior)
#pragma unroll
    for (int i = 0; i < 3; i++) {
        int idx = t + i * 256;
        if (idx < 640) {
            int c   = idx / 40;
            int rem = idx - c * 40;
            int r   = rem / 10;
            int q   = rem - r * 10;
            int hh  = h0 + r - 1;
            int wc  = w0 - 4 + q * 4;
            float* dst = xf + c * XS_CH + r * XS_ROW + q * 4;
            if ((unsigned)hh < (unsigned)H_ && wc >= 0 && wc <= (W_ - 4)) {
                const float* src = x + (((size_t)(b * C_ + c0 + c)) * H_ + hh) * W_ + wc;
                asm volatile("cp.async.cg.shared.global [%0], [%1], 16;"
                             :: "r"(smem_u32(dst)), "l"(src));
            } else {
                *reinterpret_cast<float4*>(dst) = make_float4(0.f, 0.f, 0.f, 0.f);
            }
        }
    }
}

// depthwise for chunk cj: 4 pixels x 2 output rows per thread (row reuse)
__device__ __forceinline__ void dw_chunk2(float* smem, int cj, int kch, int pxg,
                                          int wb0, bool store) {
    const float* dk = smem + DK_F;
    // dk stride 12: 3 aligned float4 loads
    const float4* dkp = reinterpret_cast<const float4*>(dk + (cj * 16 + kch) * 12);
    float4 d0 = dkp[0], d1 = dkp[1], d2 = dkp[2];
    float kk[9] = {d0.x, d0.y, d0.z, d0.w, d1.x, d1.y, d1.z, d1.w, d2.x};

    // taps: px m = pxg*4 + j at smem cols m+3..m+5 -> need cols pxg*4+3..pxg*4+8
    // load aligned cols pxg*4 .. pxg*4+7, use v[3..8]
    const float* rowb = smem + XS_F + (cj & 1) * XS_FLTS + kch * XS_CH + pxg * 4;
    float s0[4], s1[4];
#pragma unroll
    for (int j = 0; j < 4; j++) { s0[j] = 0.f; s1[j] = 0.f; }
#pragma unroll
    for (int r = 0; r < 4; r++) {
        const float* rp = rowb + r * XS_ROW;
        float4 q0 = *reinterpret_cast<const float4*>(rp);
        float4 q1 = *reinterpret_cast<const float4*>(rp + 4);
        float s8  = rp[8];
        float v[9] = {q0.x, q0.y, q0.z, q0.w, q1.x, q1.y, q1.z, q1.w, s8};
        if (r < 3) {
            float k0 = kk[r * 3 + 0], k1 = kk[r * 3 + 1], k2 = kk[r * 3 + 2];
#pragma unroll
            for (int j = 0; j < 4; j++) {
                s0[j] = fmaf(k0, v[j + 3], s0[j]);
                s0[j] = fmaf(k1, v[j + 4], s0[j]);
                s0[j] = fmaf(k2, v[j + 5], s0[j]);
            }
        }
        if (r > 0) {
            float k0 = kk[(r - 1) * 3 + 0], k1 = kk[(r - 1) * 3 + 1],
                  k2 = kk[(r - 1) * 3 + 2];
#pragma unroll
            for (int j = 0; j < 4; j++) {
                s1[j] = fmaf(k0, v[j + 3], s1[j]);
                s1[j] = fmaf(k1, v[j + 4], s1[j]);
                s1[j] = fmaf(k2, v[j + 5], s1[j]);
            }
        }
    }
    float* abase = smem + AS_F + (cj & 1) * AS_STRIDE;
#pragma unroll
    for (int j = 0; j < 4; j++) {
        uint32_t own = (uint32_t)__half_as_ushort(__float2half_rn(s0[j]));
        uint32_t partner = __shfl_xor_sync(0xffffffffu, own, 1);
        if (store)
            abase[wb0 + j * 16] =
                __uint_as_float(__byte_perm(own, partner, 0x5410));
    }
#pragma unroll
    for (int j = 0; j < 4; j++) {
        uint32_t own = (uint32_t)__half_as_ushort(__float2half_rn(s1[j]));
        uint32_t partner = __shfl_xor_sync(0xffffffffu, own, 1);
        if (store)
            abase[wb0 + 256 + j * 16] =       // row 1: mt += 2 -> +256 words
                __uint_as_float(__byte_perm(own, partner, 0x5410));
    }
}

__global__ __launch_bounds__(256, 3)
void fused_kernel(const float* __restrict__ x,
                  const float* __restrict__ pw_b,
                  float* __restrict__ out) {
    extern __shared__ float smem[];
    float* dk = smem + DK_F;

    const int t    = threadIdx.x;
    const int wid  = t >> 5;
    const int lane = t & 31;
    const int w0   = blockIdx.x * 32;
    const int h0   = blockIdx.y * 2;
    const int bb   = blockIdx.z;

    // dw mapping (threads 0-127): channel kch, px group pxg (4 px, both rows)
    const int kch = t & 15;
    const int pxg = (t >> 4) & 7;
    const bool is_dw = (t < 128);
    const int wb0 = (pxg >> 2) * 128 + (pxg & 1) * 64
                  + ((kch >> 1) & 3) * 4 + (kch >> 3) * 2 + ((pxg >> 1) & 1);
    const bool a_store = is_dw && ((kch & 1) == 0);

    // GEMM warp tiling: 2 m-warps x 4 n-warps, warp tile m32 x n32
    const int wm = wid & 1;
    const int wn = wid >> 1;
    const uint2* bsrc = g_pwf16 + (wn * 4) * 32 + lane;

    // prologue
    stage_xs(x, bb, 0, h0, w0, smem + XS_F, t);
    asm volatile("cp.async.commit_group;" ::: "memory");
    // dk padded to stride 12
    for (int i = t; i < C_ * 9; i += 256) {
        int ch = i / 9, j = i - ch * 9;
        dk[ch * 12 + j] = g_dynk[bb * C_ * 9 + i];
    }

    float acc[2][4][4];
#pragma unroll
    for (int i = 0; i < 2; i++)
#pragma unroll
        for (int j = 0; j < 4; j++)
#pragma unroll
            for (int k = 0; k < 4; k++) acc[i][j][k] = 0.f;

    asm volatile("cp.async.wait_group 0;" ::: "memory");
    __syncthreads();
    stage_xs(x, bb, 16, h0, w0, smem + XS_F + XS_FLTS, t);
    asm volatile("cp.async.commit_group;" ::: "memory");

    if (is_dw) dw_chunk2(smem, 0, kch, pxg, wb0, a_store);

#pragma unroll 1
    for (int ci = 0; ci < 8; ci++) {
        if (ci < 7)
            asm volatile("cp.async.wait_group 0;" ::: "memory");
        __syncthreads();   // dw(ci) visible; GEMM(ci-1) done with As[(ci+1)&1]

        // B fragments for GEMM(ci): direct LDG, latency covered by dw below
        uint2 bfrag[4];
#pragma unroll
        for (int ntl = 0; ntl < 4; ntl++)
            bfrag[ntl] = __ldg(bsrc + ci * 512 + ntl * 32);

        if (ci < 6) {
            stage_xs(x, bb, (ci + 2) * 16, h0, w0, smem + XS_F + (ci & 1) * XS_FLTS, t);
            asm volatile("cp.async.commit_group;" ::: "memory");
        }

        // dw(ci+1) overlaps GEMM(ci) across warps
        if (ci < 7 && is_dw)
            dw_chunk2(smem, ci + 1, kch, pxg, wb0, a_store);

        // --- GEMM(ci): one k16 MMA per (mt, nt) ---
        {
            const float* asb = smem + AS_F + (ci & 1) * AS_STRIDE;
            uint4 ah[2];
#pragma unroll
            for (int mA = 0; mA < 2; mA++) {
                int fi = ((wm * 2 + mA) * 32 + lane) * 4;
                ah[mA] = *reinterpret_cast<const uint4*>(asb + fi);
            }
#pragma unroll
            for (int ntl = 0; ntl < 4; ntl++) {
                uint2 bv = bfrag[ntl];
#pragma unroll
                for (int mA = 0; mA < 2; mA++)
                    mma_f16(acc[mA][ntl], reinterpret_cast<uint32_t*>(&ah[mA]),
                            bv.x, bv.y);
            }
        }
    }

    // --- epilogue: D fragment scatter + bias ---
    // mt = wm*2 + mA: output row = h0 + (mt>>1), px base = (mt&1)*16
    const int g   = lane >> 2;
    const int tig = lane & 3;
#pragma unroll
    for (int mA = 0; mA < 2; mA++) {
        int mt = wm * 2 + mA;
        int h  = h0 + (mt >> 1);
        int wp = w0 + (mt & 1) * 16;
#pragma unroll
        for (int ntl = 0; ntl < 4; ntl++) {
            int o = (wn * 4 + ntl) * 8 + 2 * tig;
            float b0v = __ldg(pw_b + o);
            float b1v = __ldg(pw_b + o + 1);
            size_t r0 = (((size_t)(bb * OC_ + o)) * H_ + h) * W_ + wp;
            size_t r1 = r0 + (size_t)H_ * W_;
            const float* a4 = acc[mA][ntl];
            out[r0 + g]     = a4[0] + b0v;
            out[r1 + g]     = a4[1] + b1v;
            out[r0 + g + 8] = a4[2] + b0v;
            out[r1 + g + 8] = a4[3] + b1v;
        }
    }
}

// ---------------------------------------------------------------------------
extern "C" void kernel_launch(void* const* d_in, const int* in_sizes, int n_in,
                              void* d_out, int out_size) {
    const float* x           = (const float*)d_in[0];
    const float* kernel_bank = (const float*)d_in[1];
    const float* attn_w      = (const float*)d_in[2];
    const float* attn_b      = (const float*)d_in[3];
    const float* pw_w        = (const float*)d_in[4];
    const float* pw_b        = (const float*)d_in[5];
    float* out               = (float*)d_out;

    static int smem_set = 0;
    if (!smem_set) {
        cudaFuncSetAttribute(fused_kernel,
                             cudaFuncAttributeMaxDynamicSharedMemorySize,
                             SMEM_FLOATS * 4);
        smem_set = 1;
    }

    pool_kernel<<<B_ * C_, 256>>>(x);
    prep_kernel<<<24, 256>>>(kernel_bank, attn_w, attn_b, pw_w);
    fused_kernel<<<dim3(W_ / 32, H_ / 2, B_), 256, SMEM_FLOATS * 4>>>(x, pw_b, out);
}